// round 12
// baseline (speedup 1.0000x reference)
#include <cuda_runtime.h>
#include <cuda_bf16.h>
#include <cstdint>

#define BATCH 16384
#define VAR   64
#define HID   1024
#define OUTD  32

// -------------------- device scratch (no runtime allocation) ---------------
__device__ __align__(256) __nv_bfloat16 g_Whi0[HID*VAR],  g_Wlo0[HID*VAR];
__device__ __align__(256) __nv_bfloat16 g_Whi1[HID*HID],  g_Wlo1[HID*HID];
__device__ __align__(256) __nv_bfloat16 g_Whi2[HID*HID],  g_Wlo2[HID*HID];
__device__ __align__(256) __nv_bfloat16 g_Whi3[HID*HID],  g_Wlo3[HID*HID];
__device__ __align__(256) __nv_bfloat16 g_Whi4[VAR*HID],  g_Wlo4[VAR*HID];
__device__ __align__(256) float g_tc[5*HID];
__device__ __align__(256) __nv_bfloat16 g_aHiA[BATCH*HID], g_aLoA[BATCH*HID];
__device__ __align__(256) __nv_bfloat16 g_aHiB[BATCH*HID], g_aLoB[BATCH*HID];
__device__ __align__(256) __nv_bfloat16 g_yhi[BATCH*VAR],  g_ylo[BATCH*VAR];
__device__ __align__(256) __nv_bfloat16 g_zhi[BATCH*VAR],  g_zlo[BATCH*VAR];
__device__ __align__(256) float g_y[BATCH*VAR];
__device__ __align__(256) float g_kb[2*BATCH*VAR];   // split-K partials kb0, kb1
__device__ __align__(256) float g_acc[BATCH*VAR];

// ============================ PTX helpers (baseline ISA only) ==============
__device__ __forceinline__ uint32_t smem_u32(const void* p) {
    uint32_t a;
    asm("{ .reg .u64 t; cvta.to.shared.u64 t, %1; cvt.u32.u64 %0, t; }" : "=r"(a) : "l"(p));
    return a;
}
__device__ __forceinline__ void cp16(uint32_t dst, const void* src) {
    asm volatile("cp.async.cg.shared.global [%0], [%1], 16;" :: "r"(dst), "l"(src) : "memory");
}
__device__ __forceinline__ void cp_commit() {
    asm volatile("cp.async.commit_group;" ::: "memory");
}
template <int N>
__device__ __forceinline__ void cp_wait() {
    asm volatile("cp.async.wait_group %0;" :: "n"(N) : "memory");
}
__device__ __forceinline__ void ldmx4(uint32_t* r, uint32_t addr) {
    asm volatile("ldmatrix.sync.aligned.m8n8.x4.shared.b16 {%0,%1,%2,%3}, [%4];"
                 : "=r"(r[0]), "=r"(r[1]), "=r"(r[2]), "=r"(r[3]) : "r"(addr));
}
__device__ __forceinline__ void mma16816(float* d, const uint32_t* a, const uint32_t* b) {
    asm volatile(
        "mma.sync.aligned.m16n8k16.row.col.f32.bf16.bf16.f32 "
        "{%0,%1,%2,%3}, {%4,%5,%6,%7}, {%8,%9}, {%0,%1,%2,%3};"
        : "+f"(d[0]), "+f"(d[1]), "+f"(d[2]), "+f"(d[3])
        : "r"(a[0]), "r"(a[1]), "r"(a[2]), "r"(a[3]), "r"(b[0]), "r"(b[1]));
}
__device__ __forceinline__ uint32_t pk2(__nv_bfloat16 a, __nv_bfloat16 b) {
    return (uint32_t)__bfloat16_as_ushort(a) | ((uint32_t)__bfloat16_as_ushort(b) << 16);
}
__device__ __forceinline__ void st_hilo4(__nv_bfloat16* hi, __nv_bfloat16* lo,
                                         long i4, float4 v) {
    __nv_bfloat16 h0 = __float2bfloat16(v.x), h1 = __float2bfloat16(v.y);
    __nv_bfloat16 h2 = __float2bfloat16(v.z), h3 = __float2bfloat16(v.w);
    __nv_bfloat16 l0 = __float2bfloat16(v.x - __bfloat162float(h0));
    __nv_bfloat16 l1 = __float2bfloat16(v.y - __bfloat162float(h1));
    __nv_bfloat16 l2 = __float2bfloat16(v.z - __bfloat162float(h2));
    __nv_bfloat16 l3 = __float2bfloat16(v.w - __bfloat162float(h3));
    ((uint2*)hi)[i4] = make_uint2(pk2(h0, h1), pk2(h2, h3));
    ((uint2*)lo)[i4] = make_uint2(pk2(l0, l1), pk2(l2, l3));
}

// ======================== support kernels ==================================
// One launch packs all 5 weight matrices: W[N,K+1] -> hi/lo [N,K] + tcol[N].
__global__ void pack_all(const float* __restrict__ W0, const float* __restrict__ W1,
                         const float* __restrict__ W2, const float* __restrict__ W3,
                         const float* __restrict__ W4,
                         __nv_bfloat16* h0, __nv_bfloat16* h1, __nv_bfloat16* h2,
                         __nv_bfloat16* h3, __nv_bfloat16* h4,
                         __nv_bfloat16* l0, __nv_bfloat16* l1, __nv_bfloat16* l2,
                         __nv_bfloat16* l3, __nv_bfloat16* l4,
                         float* __restrict__ tc) {
    const float* Ws[5] = {W0, W1, W2, W3, W4};
    __nv_bfloat16* His[5] = {h0, h1, h2, h3, h4};
    __nv_bfloat16* Los[5] = {l0, l1, l2, l3, l4};
    const int Ns[5] = {HID, HID, HID, HID, VAR};
    const int Ks[5] = {VAR, HID, HID, HID, HID};
    int L = blockIdx.y;
    const float* W = Ws[L];
    __nv_bfloat16* hi = His[L];
    __nv_bfloat16* lo = Los[L];
    int N = Ns[L], K = Ks[L];
    float* tcol = tc + L * HID;
    int i = blockIdx.x * blockDim.x + threadIdx.x;
    if (i < N * K) {
        int n = i / K, k = i - n * K;
        float v = W[(long)n * (K + 1) + k];
        __nv_bfloat16 h = __float2bfloat16(v);
        hi[i] = h;
        lo[i] = __float2bfloat16(v - __bfloat162float(h));
    }
    if (i < N) tcol[i] = W[(long)i * (K + 1) + K];
}

__global__ void init_y(const float* __restrict__ x, const float* __restrict__ aug,
                       float* __restrict__ y, __nv_bfloat16* __restrict__ yhi,
                       __nv_bfloat16* __restrict__ ylo) {
    int i4 = blockIdx.x * blockDim.x + threadIdx.x;
    if (i4 >= BATCH * VAR / 4) return;
    int i = i4 * 4, b = i >> 6, c = i & 63;
    float4 v = (c < 32) ? ((const float4*)x)[(b * 32 + c) >> 2]
                        : ((const float4*)aug)[(b * 32 + (c - 32)) >> 2];
    ((float4*)y)[i4] = v;
    st_hilo4(yhi, ylo, i4, v);
}

// k = kb0 + kb1 ; acc' = (mode ? acc : 0) + w*k ; z = y + cz*k -> zhi/zlo
__global__ void accz(const float* __restrict__ y, const float* __restrict__ kb0,
                     const float* __restrict__ kb1, float* __restrict__ acc,
                     __nv_bfloat16* __restrict__ zhi, __nv_bfloat16* __restrict__ zlo,
                     float w, float cz, int mode) {
    int i4 = blockIdx.x * blockDim.x + threadIdx.x;
    if (i4 >= BATCH * VAR / 4) return;
    float4 ka = ((const float4*)kb0)[i4];
    float4 kc = ((const float4*)kb1)[i4];
    float4 k = make_float4(ka.x + kc.x, ka.y + kc.y, ka.z + kc.z, ka.w + kc.w);
    float4 a;
    if (mode) {
        a = ((const float4*)acc)[i4];
        a.x = fmaf(w, k.x, a.x); a.y = fmaf(w, k.y, a.y);
        a.z = fmaf(w, k.z, a.z); a.w = fmaf(w, k.w, a.w);
    } else { a.x = w*k.x; a.y = w*k.y; a.z = w*k.z; a.w = w*k.w; }
    ((float4*)acc)[i4] = a;
    float4 yv = ((const float4*)y)[i4];
    float4 z;
    z.x = fmaf(cz, k.x, yv.x); z.y = fmaf(cz, k.y, yv.y);
    z.z = fmaf(cz, k.z, yv.z); z.w = fmaf(cz, k.w, yv.w);
    st_hilo4(zhi, zlo, i4, z);
}

// k = kb0 + kb1 ; y += sixth*(acc + k) -> y, yhi/ylo
__global__ void yupd(float* __restrict__ y, const float* __restrict__ acc,
                     const float* __restrict__ kb0, const float* __restrict__ kb1,
                     __nv_bfloat16* __restrict__ yhi, __nv_bfloat16* __restrict__ ylo,
                     float sixth) {
    int i4 = blockIdx.x * blockDim.x + threadIdx.x;
    if (i4 >= BATCH * VAR / 4) return;
    float4 a = ((const float4*)acc)[i4];
    float4 ka = ((const float4*)kb0)[i4];
    float4 kc = ((const float4*)kb1)[i4];
    float4 yv = ((float4*)y)[i4];
    yv.x = fmaf(sixth, a.x + ka.x + kc.x, yv.x);
    yv.y = fmaf(sixth, a.y + ka.y + kc.y, yv.y);
    yv.z = fmaf(sixth, a.z + ka.z + kc.z, yv.z);
    yv.w = fmaf(sixth, a.w + ka.w + kc.w, yv.w);
    ((float4*)y)[i4] = yv;
    st_hilo4(yhi, ylo, i4, yv);
}

__global__ void copy_out(const float* __restrict__ y, float* __restrict__ out) {
    int i = blockIdx.x * blockDim.x + threadIdx.x;
    if (i < BATCH * OUTD) {
        int b = i / OUTD, c = i - b * OUTD;
        out[i] = y[b * VAR + c];
    }
}

// =========================== mma.sync GEMM =================================
// C[BATCH,N] = A[BATCH,K] * B[N,K]^T + bias + t*tcol [+ReLU]
// A,B = bf16 hi/lo K-major planes. CTA tile 128 x BN, 8 warps (4x2),
// warp tile 32 x BN/2, mma m16n8k16, BK=32, cp.async 3-stage pipeline,
// ONE __syncthreads per chunk. Split-K via blockIdx.z; ONLY z==0 adds
// bias + t*tcol (partials must not duplicate the additive term).
template <int BN, bool RELU, bool OUTF32>
__global__ void __launch_bounds__(256, 1)
node_gemm(const __nv_bfloat16* __restrict__ Ahi, const __nv_bfloat16* __restrict__ Alo,
          const __nv_bfloat16* __restrict__ Bhi, const __nv_bfloat16* __restrict__ Blo,
          const float* __restrict__ bias, const float* __restrict__ tcol, float t,
          __nv_bfloat16* __restrict__ oHi, __nv_bfloat16* __restrict__ oLo,
          float* __restrict__ oF, int N, int K, int Ksub, int NC) {
    constexpr int STR   = 80;                 // smem row stride bytes (40 bf16)
    constexpr int A_BY  = 128 * STR;          // 10240
    constexpr int B_BY  = BN * STR;
    constexpr int STAGE = 2 * A_BY + 2 * B_BY;
    constexpr int NT    = BN / 16;            // n-tiles per warp (8 or 4)
    constexpr int PAIRS = NT / 2;
    constexpr int TOT   = 1024 + 8 * BN;      // cp16 ops per chunk
    constexpr int SP    = BN + 4;             // fp32 out-stage stride

    extern __shared__ char smem[];
    const uint32_t stg0 = smem_u32(smem);
    const int tid  = threadIdx.x;
    const int wid  = tid >> 5, lane = tid & 31;
    const int wm   = wid >> 1, wn = wid & 1;
    const int bn   = blockIdx.x * BN;
    const long m0  = (long)blockIdx.y * 128;
    const int koff_b = blockIdx.z * Ksub * 2;  // byte offset along K
    const float bsc = (blockIdx.z == 0) ? 1.0f : 0.0f;  // additive term once only

    const char* gA[2] = {(const char*)Ahi, (const char*)Alo};
    const char* gB[2] = {(const char*)Bhi, (const char*)Blo};
    const size_t rb = (size_t)K * 2;

    float acc[2][NT][4];
#pragma unroll
    for (int mt = 0; mt < 2; mt++)
#pragma unroll
        for (int nt = 0; nt < NT; nt++)
#pragma unroll
            for (int q = 0; q < 4; q++) acc[mt][nt][q] = 0.0f;

    // ---- issue one K-chunk of cp.async into stage c%3 ----
    auto issue = [&](int c) {
        const uint32_t sbs = stg0 + (c % 3) * STAGE;
        const int k0b = koff_b + c * 64;       // 32 bf16 = 64 bytes
#pragma unroll
        for (int it = 0; it < TOT / 256; it++) {
            int i = tid + it * 256;
            uint32_t dst; const char* src;
            if (i < 1024) {
                int pl = i >> 9, j = i & 511, r = j >> 2, q = j & 3;
                src = gA[pl] + (size_t)(m0 + r) * rb + k0b + q * 16;
                dst = sbs + pl * A_BY + r * STR + q * 16;
            } else {
                int ii = i - 1024;
                int pl = ii >= 4 * BN;
                int j = ii - pl * 4 * BN, r = j >> 2, q = j & 3;
                src = gB[pl] + (size_t)(bn + r) * rb + k0b + q * 16;
                dst = sbs + 2 * A_BY + pl * B_BY + r * STR + q * 16;
            }
            cp16(dst, src);
        }
        cp_commit();
    };

    // ldmatrix lane address components (constant across chunks)
    const int rowA  = wm * 32 + (lane & 15);            // + mt*16
    const int chA   = (lane >> 4) * 16;                 // k-chunk byte
    const int rowB  = wn * (BN / 2) + ((lane >> 4) & 1) * 8 + (lane & 7);  // + ntp*16
    const int chB   = ((lane >> 3) & 1) * 16;

    issue(0);
    if (NC > 1) issue(1);
    for (int c = 0; c < NC; c++) {
        if (c + 1 < NC) cp_wait<1>(); else cp_wait<0>();
        __syncthreads();                       // stage c visible; stage (c+2)%3 free
        if (c + 2 < NC) issue(c + 2);

        const uint32_t sbs = stg0 + (c % 3) * STAGE;
#pragma unroll
        for (int ks = 0; ks < 2; ks++) {
            uint32_t a[2][2][4];   // [plane][mt]
#pragma unroll
            for (int p = 0; p < 2; p++)
#pragma unroll
                for (int mt = 0; mt < 2; mt++)
                    ldmx4(a[p][mt], sbs + p * A_BY + (rowA + mt * 16) * STR + ks * 32 + chA);
#pragma unroll
            for (int ntp = 0; ntp < PAIRS; ntp++) {
                uint32_t bh[4], bl[4];
                uint32_t ba = sbs + 2 * A_BY + (rowB + ntp * 16) * STR + ks * 32 + chB;
                ldmx4(bh, ba);
                ldmx4(bl, ba + B_BY);
#pragma unroll
                for (int tt = 0; tt < 2; tt++) {
                    int nt = ntp * 2 + tt;
#pragma unroll
                    for (int mt = 0; mt < 2; mt++) {
                        mma16816(acc[mt][nt], a[0][mt], bh + 2 * tt);  // hi*hi
                        mma16816(acc[mt][nt], a[1][mt], bh + 2 * tt);  // lo*hi
                        mma16816(acc[mt][nt], a[0][mt], bl + 2 * tt);  // hi*lo
                    }
                }
            }
        }
    }
    __syncthreads();   // all warps done reading stages before smem reuse

    // ---- epilogue: acc -> fp32 smem stage -> bias/relu -> hi/lo (or fp32) ----
    float* stF = (float*)smem;
    {
        int r  = lane >> 2;
        int c2 = (lane & 3) * 2;
#pragma unroll
        for (int mt = 0; mt < 2; mt++)
#pragma unroll
            for (int nt = 0; nt < NT; nt++) {
                int row = wm * 32 + mt * 16 + r;
                int col = wn * (BN / 2) + nt * 8 + c2;
                stF[row * SP + col]           = acc[mt][nt][0];
                stF[row * SP + col + 1]       = acc[mt][nt][1];
                stF[(row + 8) * SP + col]     = acc[mt][nt][2];
                stF[(row + 8) * SP + col + 1] = acc[mt][nt][3];
            }
    }
    __syncthreads();

    constexpr int TASKS = 128 * (BN / 8);
#pragma unroll
    for (int it = 0; it < TASKS / 256; it++) {
        int id = tid + it * 256;
        int r = id / (BN / 8), ch = id % (BN / 8);
        int n0 = ch * 8;
        float v[8];
#pragma unroll
        for (int o = 0; o < 8; o++) {
            int n = bn + n0 + o;
            v[o] = stF[r * SP + n0 + o] + bsc * fmaf(t, tcol[n], bias[n]);
            if (RELU) v[o] = fmaxf(v[o], 0.0f);
        }
        long off = (m0 + r) * (long)N + bn + n0;
        if (OUTF32) {
            float* dst = oF + (long)blockIdx.z * (BATCH * VAR) + off;
            ((float4*)dst)[0] = make_float4(v[0], v[1], v[2], v[3]);
            ((float4*)dst)[1] = make_float4(v[4], v[5], v[6], v[7]);
        } else {
            uint32_t hp[4], lp[4];
#pragma unroll
            for (int q = 0; q < 4; q++) {
                __nv_bfloat16 h0 = __float2bfloat16(v[2*q]);
                __nv_bfloat16 h1 = __float2bfloat16(v[2*q+1]);
                hp[q] = pk2(h0, h1);
                lp[q] = pk2(__float2bfloat16(v[2*q]   - __bfloat162float(h0)),
                            __float2bfloat16(v[2*q+1] - __bfloat162float(h1)));
            }
            *(uint4*)(oHi + off) = make_uint4(hp[0], hp[1], hp[2], hp[3]);
            *(uint4*)(oLo + off) = make_uint4(lp[0], lp[1], lp[2], lp[3]);
        }
    }
}

// ---------------------------------------------------------------------------
extern "C" void kernel_launch(void* const* d_in, const int* in_sizes, int n_in,
                              void* d_out, int out_size) {
    (void)in_sizes; (void)n_in; (void)out_size;
    const float* x   = (const float*)d_in[0];
    const float* aug = (const float*)d_in[1];
    const float* W[5]; const float* bi[5];
    for (int i = 0; i < 5; i++) { W[i] = (const float*)d_in[2+2*i]; bi[i] = (const float*)d_in[3+2*i]; }
    float* out = (float*)d_out;

    __nv_bfloat16 *Whi[5], *Wlo[5], *aHiA, *aLoA, *aHiB, *aLoB, *yhi, *ylo, *zhi, *zlo;
    float *tc, *y, *kb, *acc;
    cudaGetSymbolAddress((void**)&Whi[0], g_Whi0); cudaGetSymbolAddress((void**)&Wlo[0], g_Wlo0);
    cudaGetSymbolAddress((void**)&Whi[1], g_Whi1); cudaGetSymbolAddress((void**)&Wlo[1], g_Wlo1);
    cudaGetSymbolAddress((void**)&Whi[2], g_Whi2); cudaGetSymbolAddress((void**)&Wlo[2], g_Wlo2);
    cudaGetSymbolAddress((void**)&Whi[3], g_Whi3); cudaGetSymbolAddress((void**)&Wlo[3], g_Wlo3);
    cudaGetSymbolAddress((void**)&Whi[4], g_Whi4); cudaGetSymbolAddress((void**)&Wlo[4], g_Wlo4);
    cudaGetSymbolAddress((void**)&tc,  g_tc);
    cudaGetSymbolAddress((void**)&aHiA, g_aHiA); cudaGetSymbolAddress((void**)&aLoA, g_aLoA);
    cudaGetSymbolAddress((void**)&aHiB, g_aHiB); cudaGetSymbolAddress((void**)&aLoB, g_aLoB);
    cudaGetSymbolAddress((void**)&yhi, g_yhi); cudaGetSymbolAddress((void**)&ylo, g_ylo);
    cudaGetSymbolAddress((void**)&zhi, g_zhi); cudaGetSymbolAddress((void**)&zlo, g_zlo);
    cudaGetSymbolAddress((void**)&y, g_y); cudaGetSymbolAddress((void**)&kb, g_kb);
    cudaGetSymbolAddress((void**)&acc, g_acc);
    float* kb1 = kb + BATCH * VAR;

    // dynamic smem: 3 stages of (2*A + 2*B) planes
    constexpr int SM128 = 3 * (2 * 128 * 80 + 2 * 128 * 80);   // 122880
    constexpr int SM64  = 3 * (2 * 128 * 80 + 2 * 64 * 80);    // 92160
    cudaFuncSetAttribute(node_gemm<128, true,  false>,
                         cudaFuncAttributeMaxDynamicSharedMemorySize, SM128);
    cudaFuncSetAttribute(node_gemm<64,  false, true>,
                         cudaFuncAttributeMaxDynamicSharedMemorySize, SM64);

    float* tcol[5] = {tc, tc + HID, tc + 2*HID, tc + 3*HID, tc + 4*HID};

    // launch 0: single pack for all 5 layers; launch 1: init_y
    pack_all<<<dim3(4096, 5), 256>>>(W[0], W[1], W[2], W[3], W[4],
                                     Whi[0], Whi[1], Whi[2], Whi[3], Whi[4],
                                     Wlo[0], Wlo[1], Wlo[2], Wlo[3], Wlo[4], tc);
    init_y<<<1024, 256>>>(x, aug, y, yhi, ylo);

    const float dt = 0.125f, halfd = 0.0625f, sixth = dt / 6.0f;
    dim3 gMid(HID / 128, BATCH / 128, 1);    // (8, 128)
    dim3 gLast(1, BATCH / 128, 2);           // split-K = 2

    auto eval_f = [&](float t, const __nv_bfloat16* inHi, const __nv_bfloat16* inLo) {
        node_gemm<128, true, false><<<gMid, 256, SM128>>>(
            inHi, inLo, Whi[0], Wlo[0], bi[0], tcol[0], t, aHiA, aLoA, nullptr,
            HID, VAR, VAR, 2);
        node_gemm<128, true, false><<<gMid, 256, SM128>>>(
            aHiA, aLoA, Whi[1], Wlo[1], bi[1], tcol[1], t, aHiB, aLoB, nullptr,
            HID, HID, HID, 32);
        node_gemm<128, true, false><<<gMid, 256, SM128>>>(
            aHiB, aLoB, Whi[2], Wlo[2], bi[2], tcol[2], t, aHiA, aLoA, nullptr,
            HID, HID, HID, 32);
        node_gemm<128, true, false><<<gMid, 256, SM128>>>(
            aHiA, aLoA, Whi[3], Wlo[3], bi[3], tcol[3], t, aHiB, aLoB, nullptr,
            HID, HID, HID, 32);
        node_gemm<64, false, true><<<gLast, 256, SM64>>>(
            aHiB, aLoB, Whi[4], Wlo[4], bi[4], tcol[4], t, nullptr, nullptr, kb,
            VAR, HID, HID / 2, 16);
    };

    for (int s = 0; s < 8; s++) {
        float t0 = (float)s * dt;
        eval_f(t0, yhi, ylo);                                            // k1
        accz<<<1024, 256>>>(y, kb, kb1, acc, zhi, zlo, 1.0f, halfd, 0);  // acc=k1;  z=y+dt/2*k1
        eval_f(t0 + halfd, zhi, zlo);                                    // k2
        accz<<<1024, 256>>>(y, kb, kb1, acc, zhi, zlo, 2.0f, halfd, 1);  // acc+=2k2; z=y+dt/2*k2
        eval_f(t0 + halfd, zhi, zlo);                                    // k3
        accz<<<1024, 256>>>(y, kb, kb1, acc, zhi, zlo, 2.0f, dt, 1);     // acc+=2k3; z=y+dt*k3
        eval_f(t0 + dt, zhi, zlo);                                       // k4
        yupd<<<1024, 256>>>(y, acc, kb, kb1, yhi, ylo, sixth);           // y+=dt/6*(acc+k4)
    }

    copy_out<<<(BATCH * OUTD + 255) / 256, 256>>>(y, out);
}

// round 13
// speedup vs baseline: 1.6390x; 1.6390x over previous
#include <cuda_runtime.h>
#include <cuda_bf16.h>
#include <cstdint>

#define BATCH 16384
#define VAR   64
#define HID   1024
#define OUTD  32

// -------------------- device scratch (no runtime allocation) ---------------
__device__ __align__(256) __nv_bfloat16 g_Whi0[HID*VAR],  g_Wlo0[HID*VAR];
__device__ __align__(256) __nv_bfloat16 g_Whi1[HID*HID],  g_Wlo1[HID*HID];
__device__ __align__(256) __nv_bfloat16 g_Whi2[HID*HID],  g_Wlo2[HID*HID];
__device__ __align__(256) __nv_bfloat16 g_Whi3[HID*HID],  g_Wlo3[HID*HID];
__device__ __align__(256) __nv_bfloat16 g_Whi4[VAR*HID],  g_Wlo4[VAR*HID];
__device__ __align__(256) float g_tc[5*HID];
__device__ __align__(256) __nv_bfloat16 g_aA[BATCH*HID];   // activations, bf16 single plane
__device__ __align__(256) __nv_bfloat16 g_aB[BATCH*HID];
__device__ __align__(256) __nv_bfloat16 g_yhi[BATCH*VAR],  g_ylo[BATCH*VAR];  // state hi/lo
__device__ __align__(256) __nv_bfloat16 g_zhi[BATCH*VAR],  g_zlo[BATCH*VAR];
__device__ __align__(256) float g_y[BATCH*VAR];
__device__ __align__(256) float g_kb[2*BATCH*VAR];   // split-K partials kb0, kb1
__device__ __align__(256) float g_acc[BATCH*VAR];

// ============================ PTX helpers (baseline ISA only) ==============
__device__ __forceinline__ uint32_t smem_u32(const void* p) {
    uint32_t a;
    asm("{ .reg .u64 t; cvta.to.shared.u64 t, %1; cvt.u32.u64 %0, t; }" : "=r"(a) : "l"(p));
    return a;
}
__device__ __forceinline__ void cp16(uint32_t dst, const void* src) {
    asm volatile("cp.async.cg.shared.global [%0], [%1], 16;" :: "r"(dst), "l"(src) : "memory");
}
__device__ __forceinline__ void cp_commit() {
    asm volatile("cp.async.commit_group;" ::: "memory");
}
template <int N>
__device__ __forceinline__ void cp_wait() {
    asm volatile("cp.async.wait_group %0;" :: "n"(N) : "memory");
}
__device__ __forceinline__ void ldmx4(uint32_t* r, uint32_t addr) {
    asm volatile("ldmatrix.sync.aligned.m8n8.x4.shared.b16 {%0,%1,%2,%3}, [%4];"
                 : "=r"(r[0]), "=r"(r[1]), "=r"(r[2]), "=r"(r[3]) : "r"(addr));
}
__device__ __forceinline__ void mma16816(float* d, const uint32_t* a, const uint32_t* b) {
    asm volatile(
        "mma.sync.aligned.m16n8k16.row.col.f32.bf16.bf16.f32 "
        "{%0,%1,%2,%3}, {%4,%5,%6,%7}, {%8,%9}, {%0,%1,%2,%3};"
        : "+f"(d[0]), "+f"(d[1]), "+f"(d[2]), "+f"(d[3])
        : "r"(a[0]), "r"(a[1]), "r"(a[2]), "r"(a[3]), "r"(b[0]), "r"(b[1]));
}
__device__ __forceinline__ uint32_t pk2(__nv_bfloat16 a, __nv_bfloat16 b) {
    return (uint32_t)__bfloat16_as_ushort(a) | ((uint32_t)__bfloat16_as_ushort(b) << 16);
}
__device__ __forceinline__ void st_hilo4(__nv_bfloat16* hi, __nv_bfloat16* lo,
                                         long i4, float4 v) {
    __nv_bfloat16 h0 = __float2bfloat16(v.x), h1 = __float2bfloat16(v.y);
    __nv_bfloat16 h2 = __float2bfloat16(v.z), h3 = __float2bfloat16(v.w);
    __nv_bfloat16 l0 = __float2bfloat16(v.x - __bfloat162float(h0));
    __nv_bfloat16 l1 = __float2bfloat16(v.y - __bfloat162float(h1));
    __nv_bfloat16 l2 = __float2bfloat16(v.z - __bfloat162float(h2));
    __nv_bfloat16 l3 = __float2bfloat16(v.w - __bfloat162float(h3));
    ((uint2*)hi)[i4] = make_uint2(pk2(h0, h1), pk2(h2, h3));
    ((uint2*)lo)[i4] = make_uint2(pk2(l0, l1), pk2(l2, l3));
}

// ======================== support kernels ==================================
__global__ void pack_all(const float* __restrict__ W0, const float* __restrict__ W1,
                         const float* __restrict__ W2, const float* __restrict__ W3,
                         const float* __restrict__ W4,
                         __nv_bfloat16* h0, __nv_bfloat16* h1, __nv_bfloat16* h2,
                         __nv_bfloat16* h3, __nv_bfloat16* h4,
                         __nv_bfloat16* l0, __nv_bfloat16* l1, __nv_bfloat16* l2,
                         __nv_bfloat16* l3, __nv_bfloat16* l4,
                         float* __restrict__ tc) {
    const float* Ws[5] = {W0, W1, W2, W3, W4};
    __nv_bfloat16* His[5] = {h0, h1, h2, h3, h4};
    __nv_bfloat16* Los[5] = {l0, l1, l2, l3, l4};
    const int Ns[5] = {HID, HID, HID, HID, VAR};
    const int Ks[5] = {VAR, HID, HID, HID, HID};
    int L = blockIdx.y;
    const float* W = Ws[L];
    __nv_bfloat16* hi = His[L];
    __nv_bfloat16* lo = Los[L];
    int N = Ns[L], K = Ks[L];
    float* tcol = tc + L * HID;
    int i = blockIdx.x * blockDim.x + threadIdx.x;
    if (i < N * K) {
        int n = i / K, k = i - n * K;
        float v = W[(long)n * (K + 1) + k];
        __nv_bfloat16 h = __float2bfloat16(v);
        hi[i] = h;
        lo[i] = __float2bfloat16(v - __bfloat162float(h));
    }
    if (i < N) tcol[i] = W[(long)i * (K + 1) + K];
}

__global__ void init_y(const float* __restrict__ x, const float* __restrict__ aug,
                       float* __restrict__ y, __nv_bfloat16* __restrict__ yhi,
                       __nv_bfloat16* __restrict__ ylo) {
    int i4 = blockIdx.x * blockDim.x + threadIdx.x;
    if (i4 >= BATCH * VAR / 4) return;
    int i = i4 * 4, b = i >> 6, c = i & 63;
    float4 v = (c < 32) ? ((const float4*)x)[(b * 32 + c) >> 2]
                        : ((const float4*)aug)[(b * 32 + (c - 32)) >> 2];
    ((float4*)y)[i4] = v;
    st_hilo4(yhi, ylo, i4, v);
}

// k = kb0 + kb1 ; acc' = (mode ? acc : 0) + w*k ; z = y + cz*k -> zhi/zlo
__global__ void accz(const float* __restrict__ y, const float* __restrict__ kb0,
                     const float* __restrict__ kb1, float* __restrict__ acc,
                     __nv_bfloat16* __restrict__ zhi, __nv_bfloat16* __restrict__ zlo,
                     float w, float cz, int mode) {
    int i4 = blockIdx.x * blockDim.x + threadIdx.x;
    if (i4 >= BATCH * VAR / 4) return;
    float4 ka = ((const float4*)kb0)[i4];
    float4 kc = ((const float4*)kb1)[i4];
    float4 k = make_float4(ka.x + kc.x, ka.y + kc.y, ka.z + kc.z, ka.w + kc.w);
    float4 a;
    if (mode) {
        a = ((const float4*)acc)[i4];
        a.x = fmaf(w, k.x, a.x); a.y = fmaf(w, k.y, a.y);
        a.z = fmaf(w, k.z, a.z); a.w = fmaf(w, k.w, a.w);
    } else { a.x = w*k.x; a.y = w*k.y; a.z = w*k.z; a.w = w*k.w; }
    ((float4*)acc)[i4] = a;
    float4 yv = ((const float4*)y)[i4];
    float4 z;
    z.x = fmaf(cz, k.x, yv.x); z.y = fmaf(cz, k.y, yv.y);
    z.z = fmaf(cz, k.z, yv.z); z.w = fmaf(cz, k.w, yv.w);
    st_hilo4(zhi, zlo, i4, z);
}

// k = kb0 + kb1 ; y += sixth*(acc + k) -> y, yhi/ylo
__global__ void yupd(float* __restrict__ y, const float* __restrict__ acc,
                     const float* __restrict__ kb0, const float* __restrict__ kb1,
                     __nv_bfloat16* __restrict__ yhi, __nv_bfloat16* __restrict__ ylo,
                     float sixth) {
    int i4 = blockIdx.x * blockDim.x + threadIdx.x;
    if (i4 >= BATCH * VAR / 4) return;
    float4 a = ((const float4*)acc)[i4];
    float4 ka = ((const float4*)kb0)[i4];
    float4 kc = ((const float4*)kb1)[i4];
    float4 yv = ((float4*)y)[i4];
    yv.x = fmaf(sixth, a.x + ka.x + kc.x, yv.x);
    yv.y = fmaf(sixth, a.y + ka.y + kc.y, yv.y);
    yv.z = fmaf(sixth, a.z + ka.z + kc.z, yv.z);
    yv.w = fmaf(sixth, a.w + ka.w + kc.w, yv.w);
    ((float4*)y)[i4] = yv;
    st_hilo4(yhi, ylo, i4, yv);
}

__global__ void copy_out(const float* __restrict__ y, float* __restrict__ out) {
    int i = blockIdx.x * blockDim.x + threadIdx.x;
    if (i < BATCH * OUTD) {
        int b = i / OUTD, c = i - b * OUTD;
        out[i] = y[b * VAR + c];
    }
}

// =========================== mma.sync GEMM =================================
// C[BATCH,N] = A[BATCH,K] * W[N,K]^T + bias + t*tcol [+ReLU]
// W = hi/lo bf16 pair (always). A: single bf16 plane (A2=0, 2-term) or
// hi/lo pair (A2=1, 3-term, used for the state layer). CTA 128 x BN,
// 8 warps (4x2), m16n8k16, BK=32, STAGES-deep cp.async pipeline with ONE
// __syncthreads per chunk. Split-K via blockIdx.z; only z==0 adds bias.
template <int BN, int A2, int STAGES, bool RELU, bool OUTF32>
__global__ void __launch_bounds__(256, 2)
node_gemm(const __nv_bfloat16* __restrict__ Ahi, const __nv_bfloat16* __restrict__ Alo,
          const __nv_bfloat16* __restrict__ Whi, const __nv_bfloat16* __restrict__ Wlo,
          const float* __restrict__ bias, const float* __restrict__ tcol, float t,
          __nv_bfloat16* __restrict__ oB, float* __restrict__ oF,
          int N, int K, int Ksub, int NC) {
    constexpr int STR   = 80;                 // smem row stride bytes (40 bf16)
    constexpr int A_BY  = 128 * STR;          // 10240 per A plane
    constexpr int B_BY  = BN * STR;
    constexpr int A_PL  = A2 ? 2 : 1;
    constexpr int STAGE = A_PL * A_BY + 2 * B_BY;
    constexpr int NT    = BN / 16;
    constexpr int PAIRS = NT / 2;
    constexpr int TOT   = A_PL * 512 + 8 * BN;   // cp16 ops per chunk
    constexpr int SP    = BN + 4;

    extern __shared__ char smem[];
    const uint32_t stg0 = smem_u32(smem);
    const int tid  = threadIdx.x;
    const int wid  = tid >> 5, lane = tid & 31;
    const int wm   = wid >> 1, wn = wid & 1;
    const int bn   = blockIdx.x * BN;
    const long m0  = (long)blockIdx.y * 128;
    const int koff_b = blockIdx.z * Ksub * 2;
    const float bsc = (blockIdx.z == 0) ? 1.0f : 0.0f;

    const char* gA[2] = {(const char*)Ahi, (const char*)Alo};
    const char* gB[2] = {(const char*)Whi, (const char*)Wlo};
    const size_t rb = (size_t)K * 2;

    float acc[2][NT][4];
#pragma unroll
    for (int mt = 0; mt < 2; mt++)
#pragma unroll
        for (int nt = 0; nt < NT; nt++)
#pragma unroll
            for (int q = 0; q < 4; q++) acc[mt][nt][q] = 0.0f;

    auto issue = [&](int c) {
        const uint32_t sbs = stg0 + (c % STAGES) * STAGE;
        const int k0b = koff_b + c * 64;
#pragma unroll
        for (int it = 0; it < (TOT + 255) / 256; it++) {
            int i = tid + it * 256;
            if (TOT % 256 != 0 && i >= TOT) break;
            uint32_t dst; const char* src;
            if (i < A_PL * 512) {
                int pl = i >> 9, j = i & 511, r = j >> 2, q = j & 3;
                src = gA[pl] + (size_t)(m0 + r) * rb + k0b + q * 16;
                dst = sbs + pl * A_BY + r * STR + q * 16;
            } else {
                int ii = i - A_PL * 512;
                int pl = ii >= 4 * BN;
                int j = ii - pl * 4 * BN, r = j >> 2, q = j & 3;
                src = gB[pl] + (size_t)(bn + r) * rb + k0b + q * 16;
                dst = sbs + A_PL * A_BY + pl * B_BY + r * STR + q * 16;
            }
            cp16(dst, src);
        }
        cp_commit();
    };

    const int rowA = wm * 32 + (lane & 15);
    const int chA  = (lane >> 4) * 16;
    const int rowB = wn * (BN / 2) + ((lane >> 4) & 1) * 8 + (lane & 7);
    const int chB  = ((lane >> 3) & 1) * 16;

    issue(0);
    if (STAGES >= 3 && NC > 1) issue(1);
    for (int c = 0; c < NC; c++) {
        if (STAGES == 2) cp_wait<0>();
        else { if (c + 1 < NC) cp_wait<1>(); else cp_wait<0>(); }
        __syncthreads();                       // stage c visible; oldest stage free
        if (c + STAGES - 1 < NC) issue(c + STAGES - 1);

        const uint32_t sbs = stg0 + (c % STAGES) * STAGE;
#pragma unroll
        for (int ks = 0; ks < 2; ks++) {
            uint32_t a[A_PL][2][4];
#pragma unroll
            for (int p = 0; p < A_PL; p++)
#pragma unroll
                for (int mt = 0; mt < 2; mt++)
                    ldmx4(a[p][mt], sbs + p * A_BY + (rowA + mt * 16) * STR + ks * 32 + chA);
#pragma unroll
            for (int ntp = 0; ntp < PAIRS; ntp++) {
                uint32_t bh[4], bl[4];
                uint32_t ba = sbs + A_PL * A_BY + (rowB + ntp * 16) * STR + ks * 32 + chB;
                ldmx4(bh, ba);
                ldmx4(bl, ba + B_BY);
#pragma unroll
                for (int tt = 0; tt < 2; tt++) {
                    int nt = ntp * 2 + tt;
#pragma unroll
                    for (int mt = 0; mt < 2; mt++) {
                        mma16816(acc[mt][nt], a[0][mt], bh + 2 * tt);      // Ahi*Whi
                        if (A2) mma16816(acc[mt][nt], a[1][mt], bh + 2 * tt);  // Alo*Whi
                        mma16816(acc[mt][nt], a[0][mt], bl + 2 * tt);      // Ahi*Wlo
                    }
                }
            }
        }
    }
    __syncthreads();

    // ---- epilogue: acc -> fp32 smem stage -> bias/relu -> bf16 (or fp32) ----
    float* stF = (float*)smem;
    {
        int r  = lane >> 2;
        int c2 = (lane & 3) * 2;
#pragma unroll
        for (int mt = 0; mt < 2; mt++)
#pragma unroll
            for (int nt = 0; nt < NT; nt++) {
                int row = wm * 32 + mt * 16 + r;
                int col = wn * (BN / 2) + nt * 8 + c2;
                stF[row * SP + col]           = acc[mt][nt][0];
                stF[row * SP + col + 1]       = acc[mt][nt][1];
                stF[(row + 8) * SP + col]     = acc[mt][nt][2];
                stF[(row + 8) * SP + col + 1] = acc[mt][nt][3];
            }
    }
    __syncthreads();

    constexpr int TASKS = 128 * (BN / 8);
#pragma unroll
    for (int it = 0; it < TASKS / 256; it++) {
        int id = tid + it * 256;
        int r = id / (BN / 8), ch = id % (BN / 8);
        int n0 = ch * 8;
        float v[8];
#pragma unroll
        for (int o = 0; o < 8; o++) {
            int n = bn + n0 + o;
            v[o] = stF[r * SP + n0 + o] + bsc * fmaf(t, tcol[n], bias[n]);
            if (RELU) v[o] = fmaxf(v[o], 0.0f);
        }
        long off = (m0 + r) * (long)N + bn + n0;
        if (OUTF32) {
            float* dst = oF + (long)blockIdx.z * (BATCH * VAR) + off;
            ((float4*)dst)[0] = make_float4(v[0], v[1], v[2], v[3]);
            ((float4*)dst)[1] = make_float4(v[4], v[5], v[6], v[7]);
        } else {
            uint32_t hp[4];
#pragma unroll
            for (int q = 0; q < 4; q++)
                hp[q] = pk2(__float2bfloat16(v[2*q]), __float2bfloat16(v[2*q+1]));
            *(uint4*)(oB + off) = make_uint4(hp[0], hp[1], hp[2], hp[3]);
        }
    }
}

// ---------------------------------------------------------------------------
extern "C" void kernel_launch(void* const* d_in, const int* in_sizes, int n_in,
                              void* d_out, int out_size) {
    (void)in_sizes; (void)n_in; (void)out_size;
    const float* x   = (const float*)d_in[0];
    const float* aug = (const float*)d_in[1];
    const float* W[5]; const float* bi[5];
    for (int i = 0; i < 5; i++) { W[i] = (const float*)d_in[2+2*i]; bi[i] = (const float*)d_in[3+2*i]; }
    float* out = (float*)d_out;

    __nv_bfloat16 *Whi[5], *Wlo[5], *aA, *aB, *yhi, *ylo, *zhi, *zlo;
    float *tc, *y, *kb, *acc;
    cudaGetSymbolAddress((void**)&Whi[0], g_Whi0); cudaGetSymbolAddress((void**)&Wlo[0], g_Wlo0);
    cudaGetSymbolAddress((void**)&Whi[1], g_Whi1); cudaGetSymbolAddress((void**)&Wlo[1], g_Wlo1);
    cudaGetSymbolAddress((void**)&Whi[2], g_Whi2); cudaGetSymbolAddress((void**)&Wlo[2], g_Wlo2);
    cudaGetSymbolAddress((void**)&Whi[3], g_Whi3); cudaGetSymbolAddress((void**)&Wlo[3], g_Wlo3);
    cudaGetSymbolAddress((void**)&Whi[4], g_Whi4); cudaGetSymbolAddress((void**)&Wlo[4], g_Wlo4);
    cudaGetSymbolAddress((void**)&tc,  g_tc);
    cudaGetSymbolAddress((void**)&aA, g_aA);
    cudaGetSymbolAddress((void**)&aB, g_aB);
    cudaGetSymbolAddress((void**)&yhi, g_yhi); cudaGetSymbolAddress((void**)&ylo, g_ylo);
    cudaGetSymbolAddress((void**)&zhi, g_zhi); cudaGetSymbolAddress((void**)&zlo, g_zlo);
    cudaGetSymbolAddress((void**)&y, g_y); cudaGetSymbolAddress((void**)&kb, g_kb);
    cudaGetSymbolAddress((void**)&acc, g_acc);
    float* kb1 = kb + BATCH * VAR;

    // smem: L0 (A2, 2 stages): 2*(2*10240+2*10240)=81920
    //       mid (2-term, 3 stages): 3*(10240+2*10240)=92160
    //       last (2-term, 3 stages, BN=64): 3*(10240+2*5120)=61440
    constexpr int SM_L0  = 2 * (2 * 10240 + 2 * 10240);
    constexpr int SM_MID = 3 * (10240 + 2 * 10240);
    constexpr int SM_LST = 3 * (10240 + 2 * 64 * 80);
    cudaFuncSetAttribute(node_gemm<128, 1, 2, true,  false>,
                         cudaFuncAttributeMaxDynamicSharedMemorySize, SM_L0);
    cudaFuncSetAttribute(node_gemm<128, 0, 3, true,  false>,
                         cudaFuncAttributeMaxDynamicSharedMemorySize, SM_MID);
    cudaFuncSetAttribute(node_gemm<64,  0, 3, false, true>,
                         cudaFuncAttributeMaxDynamicSharedMemorySize, SM_LST);

    float* tcol[5] = {tc, tc + HID, tc + 2*HID, tc + 3*HID, tc + 4*HID};

    pack_all<<<dim3(4096, 5), 256>>>(W[0], W[1], W[2], W[3], W[4],
                                     Whi[0], Whi[1], Whi[2], Whi[3], Whi[4],
                                     Wlo[0], Wlo[1], Wlo[2], Wlo[3], Wlo[4], tc);
    init_y<<<1024, 256>>>(x, aug, y, yhi, ylo);

    const float dt = 0.125f, halfd = 0.0625f, sixth = dt / 6.0f;
    dim3 gMid(HID / 128, BATCH / 128, 1);    // (8, 128)
    dim3 gLast(1, BATCH / 128, 2);           // split-K = 2

    auto eval_f = [&](float t, const __nv_bfloat16* inHi, const __nv_bfloat16* inLo) {
        node_gemm<128, 1, 2, true, false><<<gMid, 256, SM_L0>>>(
            inHi, inLo, Whi[0], Wlo[0], bi[0], tcol[0], t, aA, nullptr,
            HID, VAR, VAR, 2);
        node_gemm<128, 0, 3, true, false><<<gMid, 256, SM_MID>>>(
            aA, nullptr, Whi[1], Wlo[1], bi[1], tcol[1], t, aB, nullptr,
            HID, HID, HID, 32);
        node_gemm<128, 0, 3, true, false><<<gMid, 256, SM_MID>>>(
            aB, nullptr, Whi[2], Wlo[2], bi[2], tcol[2], t, aA, nullptr,
            HID, HID, HID, 32);
        node_gemm<128, 0, 3, true, false><<<gMid, 256, SM_MID>>>(
            aA, nullptr, Whi[3], Wlo[3], bi[3], tcol[3], t, aB, nullptr,
            HID, HID, HID, 32);
        node_gemm<64, 0, 3, false, true><<<gLast, 256, SM_LST>>>(
            aB, nullptr, Whi[4], Wlo[4], bi[4], tcol[4], t, nullptr, kb,
            VAR, HID, HID / 2, 16);
    };

    for (int s = 0; s < 8; s++) {
        float t0 = (float)s * dt;
        eval_f(t0, yhi, ylo);                                            // k1
        accz<<<1024, 256>>>(y, kb, kb1, acc, zhi, zlo, 1.0f, halfd, 0);  // acc=k1;  z=y+dt/2*k1
        eval_f(t0 + halfd, zhi, zlo);                                    // k2
        accz<<<1024, 256>>>(y, kb, kb1, acc, zhi, zlo, 2.0f, halfd, 1);  // acc+=2k2; z=y+dt/2*k2
        eval_f(t0 + halfd, zhi, zlo);                                    // k3
        accz<<<1024, 256>>>(y, kb, kb1, acc, zhi, zlo, 2.0f, dt, 1);     // acc+=2k3; z=y+dt*k3
        eval_f(t0 + dt, zhi, zlo);                                       // k4
        yupd<<<1024, 256>>>(y, acc, kb, kb1, yhi, ylo, sixth);           // y+=dt/6*(acc+k4)
    }

    copy_out<<<(BATCH * OUTD + 255) / 256, 256>>>(y, out);
}

// round 14
// speedup vs baseline: 1.8883x; 1.1521x over previous
#include <cuda_runtime.h>
#include <cuda_bf16.h>
#include <cstdint>

#define BATCH 16384
#define VAR   64
#define HID   1024
#define OUTD  32

// -------------------- device scratch (no runtime allocation) ---------------
__device__ __align__(256) __nv_bfloat16 g_Whi0[HID*VAR],  g_Wlo0[HID*VAR];
__device__ __align__(256) __nv_bfloat16 g_Whi1[HID*HID],  g_Wlo1[HID*HID];
__device__ __align__(256) __nv_bfloat16 g_Whi2[HID*HID],  g_Wlo2[HID*HID];
__device__ __align__(256) __nv_bfloat16 g_Whi3[HID*HID],  g_Wlo3[HID*HID];
__device__ __align__(256) __nv_bfloat16 g_Whi4[VAR*HID],  g_Wlo4[VAR*HID];
__device__ __align__(256) float g_tc[5*HID];
__device__ __align__(256) __nv_bfloat16 g_aA[BATCH*HID];   // activations, bf16
__device__ __align__(256) __nv_bfloat16 g_aB[BATCH*HID];
__device__ __align__(256) __nv_bfloat16 g_yhi[BATCH*VAR],  g_ylo[BATCH*VAR];  // state hi/lo
__device__ __align__(256) __nv_bfloat16 g_zhi[BATCH*VAR],  g_zlo[BATCH*VAR];
__device__ __align__(256) float g_y[BATCH*VAR];
__device__ __align__(256) float g_kb[2*BATCH*VAR];   // split-K partials
__device__ __align__(256) float g_acc[BATCH*VAR];

// ============================ PTX helpers ==================================
__device__ __forceinline__ uint32_t smem_u32(const void* p) {
    uint32_t a;
    asm("{ .reg .u64 t; cvta.to.shared.u64 t, %1; cvt.u32.u64 %0, t; }" : "=r"(a) : "l"(p));
    return a;
}
__device__ __forceinline__ void cp16(uint32_t dst, const void* src) {
    asm volatile("cp.async.cg.shared.global [%0], [%1], 16;" :: "r"(dst), "l"(src) : "memory");
}
__device__ __forceinline__ void cp_commit() {
    asm volatile("cp.async.commit_group;" ::: "memory");
}
template <int N>
__device__ __forceinline__ void cp_wait() {
    asm volatile("cp.async.wait_group %0;" :: "n"(N) : "memory");
}
__device__ __forceinline__ void ldmx4(uint32_t* r, uint32_t addr) {
    asm volatile("ldmatrix.sync.aligned.m8n8.x4.shared.b16 {%0,%1,%2,%3}, [%4];"
                 : "=r"(r[0]), "=r"(r[1]), "=r"(r[2]), "=r"(r[3]) : "r"(addr));
}
__device__ __forceinline__ void mma16816(float* d, const uint32_t* a, const uint32_t* b) {
    asm volatile(
        "mma.sync.aligned.m16n8k16.row.col.f32.bf16.bf16.f32 "
        "{%0,%1,%2,%3}, {%4,%5,%6,%7}, {%8,%9}, {%0,%1,%2,%3};"
        : "+f"(d[0]), "+f"(d[1]), "+f"(d[2]), "+f"(d[3])
        : "r"(a[0]), "r"(a[1]), "r"(a[2]), "r"(a[3]), "r"(b[0]), "r"(b[1]));
}
__device__ __forceinline__ uint32_t pk2(__nv_bfloat16 a, __nv_bfloat16 b) {
    return (uint32_t)__bfloat16_as_ushort(a) | ((uint32_t)__bfloat16_as_ushort(b) << 16);
}
__device__ __forceinline__ void st_hilo4(__nv_bfloat16* hi, __nv_bfloat16* lo,
                                         long i4, float4 v) {
    __nv_bfloat16 h0 = __float2bfloat16(v.x), h1 = __float2bfloat16(v.y);
    __nv_bfloat16 h2 = __float2bfloat16(v.z), h3 = __float2bfloat16(v.w);
    __nv_bfloat16 l0 = __float2bfloat16(v.x - __bfloat162float(h0));
    __nv_bfloat16 l1 = __float2bfloat16(v.y - __bfloat162float(h1));
    __nv_bfloat16 l2 = __float2bfloat16(v.z - __bfloat162float(h2));
    __nv_bfloat16 l3 = __float2bfloat16(v.w - __bfloat162float(h3));
    ((uint2*)hi)[i4] = make_uint2(pk2(h0, h1), pk2(h2, h3));
    ((uint2*)lo)[i4] = make_uint2(pk2(l0, l1), pk2(l2, l3));
}

// ======================== support kernels ==================================
__global__ void pack_all(const float* __restrict__ W0, const float* __restrict__ W1,
                         const float* __restrict__ W2, const float* __restrict__ W3,
                         const float* __restrict__ W4,
                         __nv_bfloat16* h0, __nv_bfloat16* h1, __nv_bfloat16* h2,
                         __nv_bfloat16* h3, __nv_bfloat16* h4,
                         __nv_bfloat16* l0, __nv_bfloat16* l1, __nv_bfloat16* l2,
                         __nv_bfloat16* l3, __nv_bfloat16* l4,
                         float* __restrict__ tc) {
    const float* Ws[5] = {W0, W1, W2, W3, W4};
    __nv_bfloat16* His[5] = {h0, h1, h2, h3, h4};
    __nv_bfloat16* Los[5] = {l0, l1, l2, l3, l4};
    const int Ns[5] = {HID, HID, HID, HID, VAR};
    const int Ks[5] = {VAR, HID, HID, HID, HID};
    int L = blockIdx.y;
    const float* W = Ws[L];
    __nv_bfloat16* hi = His[L];
    __nv_bfloat16* lo = Los[L];
    int N = Ns[L], K = Ks[L];
    float* tcol = tc + L * HID;
    int i = blockIdx.x * blockDim.x + threadIdx.x;
    if (i < N * K) {
        int n = i / K, k = i - n * K;
        float v = W[(long)n * (K + 1) + k];
        __nv_bfloat16 h = __float2bfloat16(v);
        hi[i] = h;
        lo[i] = __float2bfloat16(v - __bfloat162float(h));
    }
    if (i < N) tcol[i] = W[(long)i * (K + 1) + K];
}

__global__ void init_y(const float* __restrict__ x, const float* __restrict__ aug,
                       float* __restrict__ y, __nv_bfloat16* __restrict__ yhi,
                       __nv_bfloat16* __restrict__ ylo) {
    int i4 = blockIdx.x * blockDim.x + threadIdx.x;
    if (i4 >= BATCH * VAR / 4) return;
    int i = i4 * 4, b = i >> 6, c = i & 63;
    float4 v = (c < 32) ? ((const float4*)x)[(b * 32 + c) >> 2]
                        : ((const float4*)aug)[(b * 32 + (c - 32)) >> 2];
    ((float4*)y)[i4] = v;
    st_hilo4(yhi, ylo, i4, v);
}

__global__ void accz(const float* __restrict__ y, const float* __restrict__ kb0,
                     const float* __restrict__ kb1, float* __restrict__ acc,
                     __nv_bfloat16* __restrict__ zhi, __nv_bfloat16* __restrict__ zlo,
                     float w, float cz, int mode) {
    int i4 = blockIdx.x * blockDim.x + threadIdx.x;
    if (i4 >= BATCH * VAR / 4) return;
    float4 ka = ((const float4*)kb0)[i4];
    float4 kc = ((const float4*)kb1)[i4];
    float4 k = make_float4(ka.x + kc.x, ka.y + kc.y, ka.z + kc.z, ka.w + kc.w);
    float4 a;
    if (mode) {
        a = ((const float4*)acc)[i4];
        a.x = fmaf(w, k.x, a.x); a.y = fmaf(w, k.y, a.y);
        a.z = fmaf(w, k.z, a.z); a.w = fmaf(w, k.w, a.w);
    } else { a.x = w*k.x; a.y = w*k.y; a.z = w*k.z; a.w = w*k.w; }
    ((float4*)acc)[i4] = a;
    float4 yv = ((const float4*)y)[i4];
    float4 z;
    z.x = fmaf(cz, k.x, yv.x); z.y = fmaf(cz, k.y, yv.y);
    z.z = fmaf(cz, k.z, yv.z); z.w = fmaf(cz, k.w, yv.w);
    st_hilo4(zhi, zlo, i4, z);
}

__global__ void yupd(float* __restrict__ y, const float* __restrict__ acc,
                     const float* __restrict__ kb0, const float* __restrict__ kb1,
                     __nv_bfloat16* __restrict__ yhi, __nv_bfloat16* __restrict__ ylo,
                     float sixth) {
    int i4 = blockIdx.x * blockDim.x + threadIdx.x;
    if (i4 >= BATCH * VAR / 4) return;
    float4 a = ((const float4*)acc)[i4];
    float4 ka = ((const float4*)kb0)[i4];
    float4 kc = ((const float4*)kb1)[i4];
    float4 yv = ((float4*)y)[i4];
    yv.x = fmaf(sixth, a.x + ka.x + kc.x, yv.x);
    yv.y = fmaf(sixth, a.y + ka.y + kc.y, yv.y);
    yv.z = fmaf(sixth, a.z + ka.z + kc.z, yv.z);
    yv.w = fmaf(sixth, a.w + ka.w + kc.w, yv.w);
    ((float4*)y)[i4] = yv;
    st_hilo4(yhi, ylo, i4, yv);
}

__global__ void copy_out(const float* __restrict__ y, float* __restrict__ out) {
    int i = blockIdx.x * blockDim.x + threadIdx.x;
    if (i < BATCH * OUTD) {
        int b = i / OUTD, c = i - b * OUTD;
        out[i] = y[b * VAR + c];
    }
}

// =========================== mma.sync GEMM =================================
// C[BATCH,N] = A[BATCH,K] * W[N,K]^T + bias + t*tcol [+ReLU]
// W = hi/lo bf16 pair. A: 1 plane (A2=0) or hi/lo pair (A2=1).
// CTA 128 x BN, 8 warps (4x2), m16n8k16, K-chunk = KB bf16 (32 or 64),
// 2-stage cp.async pipeline, ONE __syncthreads per chunk.
// Split-K via blockIdx.z; only z==0 adds bias + t*tcol.
template <int BN, int A2, int KB, bool RELU, bool OUTF32>
__global__ void __launch_bounds__(256, 2)
node_gemm(const __nv_bfloat16* __restrict__ Ahi, const __nv_bfloat16* __restrict__ Alo,
          const __nv_bfloat16* __restrict__ Whi, const __nv_bfloat16* __restrict__ Wlo,
          const float* __restrict__ bias, const float* __restrict__ tcol, float t,
          __nv_bfloat16* __restrict__ oB, float* __restrict__ oF,
          int N, int K, int Ksub, int NC) {
    constexpr int STR   = KB * 2 + 16;          // smem row stride bytes (+16 pad)
    constexpr int A_BY  = 128 * STR;
    constexpr int B_BY  = BN * STR;
    constexpr int A_PL  = A2 ? 2 : 1;
    constexpr int STAGE = A_PL * A_BY + 2 * B_BY;
    constexpr int NT    = BN / 16;
    constexpr int PAIRS = NT / 2;
    constexpr int QPR   = KB / 8;               // 16B ops per row per chunk
    constexpr int A_OPS = 128 * QPR;            // per A plane
    constexpr int B_OPS = BN * QPR;             // per B plane
    constexpr int TOT   = A_PL * A_OPS + 2 * B_OPS;
    constexpr int KS    = KB / 16;              // mma k-steps per chunk
    constexpr int SP    = BN + 4;

    extern __shared__ char smem[];
    const uint32_t stg0 = smem_u32(smem);
    const int tid  = threadIdx.x;
    const int wid  = tid >> 5, lane = tid & 31;
    const int wm   = wid >> 1, wn = wid & 1;
    const int bn   = blockIdx.x * BN;
    const long m0  = (long)blockIdx.y * 128;
    const int koff_b = blockIdx.z * Ksub * 2;
    const float bsc = (blockIdx.z == 0) ? 1.0f : 0.0f;

    const char* gA[2] = {(const char*)Ahi, (const char*)Alo};
    const char* gB[2] = {(const char*)Whi, (const char*)Wlo};
    const size_t rb = (size_t)K * 2;

    float acc[2][NT][4];
#pragma unroll
    for (int mt = 0; mt < 2; mt++)
#pragma unroll
        for (int nt = 0; nt < NT; nt++)
#pragma unroll
            for (int q = 0; q < 4; q++) acc[mt][nt][q] = 0.0f;

    auto issue = [&](int c) {
        const uint32_t sbs = stg0 + (c & 1) * STAGE;
        const int k0b = koff_b + c * (KB * 2);
#pragma unroll
        for (int it = 0; it < (TOT + 255) / 256; it++) {
            int i = tid + it * 256;
            if (TOT % 256 != 0 && i >= TOT) break;
            uint32_t dst; const char* src;
            if (i < A_PL * A_OPS) {
                int pl = i / A_OPS, j = i % A_OPS;
                int r = j / QPR, q = j % QPR;
                src = gA[pl] + (size_t)(m0 + r) * rb + k0b + q * 16;
                dst = sbs + pl * A_BY + r * STR + q * 16;
            } else {
                int ii = i - A_PL * A_OPS;
                int pl = ii / B_OPS, j = ii % B_OPS;
                int r = j / QPR, q = j % QPR;
                src = gB[pl] + (size_t)(bn + r) * rb + k0b + q * 16;
                dst = sbs + A_PL * A_BY + pl * B_BY + r * STR + q * 16;
            }
            cp16(dst, src);
        }
        cp_commit();
    };

    const int rowA = wm * 32 + (lane & 15);
    const int chA  = (lane >> 4) * 16;
    const int rowB = wn * (BN / 2) + ((lane >> 4) & 1) * 8 + (lane & 7);
    const int chB  = ((lane >> 3) & 1) * 16;

    issue(0);
    for (int c = 0; c < NC; c++) {
        cp_wait<0>();                         // stage c landed
        __syncthreads();                      // all warps done with stage c-1
        if (c + 1 < NC) issue(c + 1);         // refill the dead stage (async)

        const uint32_t sbs = stg0 + (c & 1) * STAGE;
#pragma unroll
        for (int ks = 0; ks < KS; ks++) {
            uint32_t a[A_PL][2][4];
#pragma unroll
            for (int p = 0; p < A_PL; p++)
#pragma unroll
                for (int mt = 0; mt < 2; mt++)
                    ldmx4(a[p][mt], sbs + p * A_BY + (rowA + mt * 16) * STR + ks * 32 + chA);
#pragma unroll
            for (int ntp = 0; ntp < PAIRS; ntp++) {
                uint32_t bh[4], bl[4];
                uint32_t ba = sbs + A_PL * A_BY + (rowB + ntp * 16) * STR + ks * 32 + chB;
                ldmx4(bh, ba);
                ldmx4(bl, ba + B_BY);
#pragma unroll
                for (int tt = 0; tt < 2; tt++) {
                    int nt = ntp * 2 + tt;
#pragma unroll
                    for (int mt = 0; mt < 2; mt++) {
                        mma16816(acc[mt][nt], a[0][mt], bh + 2 * tt);          // Ahi*Whi
                        if (A2) mma16816(acc[mt][nt], a[1][mt], bh + 2 * tt);  // Alo*Whi
                        mma16816(acc[mt][nt], a[0][mt], bl + 2 * tt);          // Ahi*Wlo
                    }
                }
            }
        }
    }
    __syncthreads();

    // ---- epilogue: acc -> fp32 smem stage -> bias/relu -> bf16 (or fp32) ----
    float* stF = (float*)smem;
    {
        int r  = lane >> 2;
        int c2 = (lane & 3) * 2;
#pragma unroll
        for (int mt = 0; mt < 2; mt++)
#pragma unroll
            for (int nt = 0; nt < NT; nt++) {
                int row = wm * 32 + mt * 16 + r;
                int col = wn * (BN / 2) + nt * 8 + c2;
                stF[row * SP + col]           = acc[mt][nt][0];
                stF[row * SP + col + 1]       = acc[mt][nt][1];
                stF[(row + 8) * SP + col]     = acc[mt][nt][2];
                stF[(row + 8) * SP + col + 1] = acc[mt][nt][3];
            }
    }
    __syncthreads();

    constexpr int TASKS = 128 * (BN / 8);
#pragma unroll
    for (int it = 0; it < TASKS / 256; it++) {
        int id = tid + it * 256;
        int r = id / (BN / 8), ch = id % (BN / 8);
        int n0 = ch * 8;
        float v[8];
#pragma unroll
        for (int o = 0; o < 8; o++) {
            int n = bn + n0 + o;
            v[o] = stF[r * SP + n0 + o] + bsc * fmaf(t, tcol[n], bias[n]);
            if (RELU) v[o] = fmaxf(v[o], 0.0f);
        }
        long off = (m0 + r) * (long)N + bn + n0;
        if (OUTF32) {
            float* dst = oF + (long)blockIdx.z * (BATCH * VAR) + off;
            ((float4*)dst)[0] = make_float4(v[0], v[1], v[2], v[3]);
            ((float4*)dst)[1] = make_float4(v[4], v[5], v[6], v[7]);
        } else {
            uint32_t hp[4];
#pragma unroll
            for (int q = 0; q < 4; q++)
                hp[q] = pk2(__float2bfloat16(v[2*q]), __float2bfloat16(v[2*q+1]));
            *(uint4*)(oB + off) = make_uint4(hp[0], hp[1], hp[2], hp[3]);
        }
    }
}

// ---------------------------------------------------------------------------
extern "C" void kernel_launch(void* const* d_in, const int* in_sizes, int n_in,
                              void* d_out, int out_size) {
    (void)in_sizes; (void)n_in; (void)out_size;
    const float* x   = (const float*)d_in[0];
    const float* aug = (const float*)d_in[1];
    const float* W[5]; const float* bi[5];
    for (int i = 0; i < 5; i++) { W[i] = (const float*)d_in[2+2*i]; bi[i] = (const float*)d_in[3+2*i]; }
    float* out = (float*)d_out;

    __nv_bfloat16 *Whi[5], *Wlo[5], *aA, *aB, *yhi, *ylo, *zhi, *zlo;
    float *tc, *y, *kb, *acc;
    cudaGetSymbolAddress((void**)&Whi[0], g_Whi0); cudaGetSymbolAddress((void**)&Wlo[0], g_Wlo0);
    cudaGetSymbolAddress((void**)&Whi[1], g_Whi1); cudaGetSymbolAddress((void**)&Wlo[1], g_Wlo1);
    cudaGetSymbolAddress((void**)&Whi[2], g_Whi2); cudaGetSymbolAddress((void**)&Wlo[2], g_Wlo2);
    cudaGetSymbolAddress((void**)&Whi[3], g_Whi3); cudaGetSymbolAddress((void**)&Wlo[3], g_Wlo3);
    cudaGetSymbolAddress((void**)&Whi[4], g_Whi4); cudaGetSymbolAddress((void**)&Wlo[4], g_Wlo4);
    cudaGetSymbolAddress((void**)&tc,  g_tc);
    cudaGetSymbolAddress((void**)&aA, g_aA);
    cudaGetSymbolAddress((void**)&aB, g_aB);
    cudaGetSymbolAddress((void**)&yhi, g_yhi); cudaGetSymbolAddress((void**)&ylo, g_ylo);
    cudaGetSymbolAddress((void**)&zhi, g_zhi); cudaGetSymbolAddress((void**)&zlo, g_zlo);
    cudaGetSymbolAddress((void**)&y, g_y); cudaGetSymbolAddress((void**)&kb, g_kb);
    cudaGetSymbolAddress((void**)&acc, g_acc);
    float* kb1 = kb + BATCH * VAR;

    // smem budgets:
    //   L0  (A2=1, KB=32): 2*(2*10240 + 2*10240)         = 81920
    //   mid (A2=0, KB=64): 2*(18432 + 2*18432)           = 110592  (2 CTA/SM: 221KB)
    //   last(A2=0, KB=64, BN=64): 2*(18432 + 2*9216)     = 73728
    constexpr int SM_L0  = 2 * (2 * 128 * 80 + 2 * 128 * 80);
    constexpr int SM_MID = 2 * (128 * 144 + 2 * 128 * 144);
    constexpr int SM_LST = 2 * (128 * 144 + 2 * 64 * 144);
    cudaFuncSetAttribute(node_gemm<128, 1, 32, true,  false>,
                         cudaFuncAttributeMaxDynamicSharedMemorySize, SM_L0);
    cudaFuncSetAttribute(node_gemm<128, 0, 64, true,  false>,
                         cudaFuncAttributeMaxDynamicSharedMemorySize, SM_MID);
    cudaFuncSetAttribute(node_gemm<64,  0, 64, false, true>,
                         cudaFuncAttributeMaxDynamicSharedMemorySize, SM_LST);

    float* tcol[5] = {tc, tc + HID, tc + 2*HID, tc + 3*HID, tc + 4*HID};

    pack_all<<<dim3(4096, 5), 256>>>(W[0], W[1], W[2], W[3], W[4],
                                     Whi[0], Whi[1], Whi[2], Whi[3], Whi[4],
                                     Wlo[0], Wlo[1], Wlo[2], Wlo[3], Wlo[4], tc);
    init_y<<<1024, 256>>>(x, aug, y, yhi, ylo);

    const float dt = 0.125f, halfd = 0.0625f, sixth = dt / 6.0f;
    dim3 gMid(HID / 128, BATCH / 128, 1);    // (8, 128)
    dim3 gLast(1, BATCH / 128, 2);           // split-K = 2

    auto eval_f = [&](float t, const __nv_bfloat16* inHi, const __nv_bfloat16* inLo) {
        node_gemm<128, 1, 32, true, false><<<gMid, 256, SM_L0>>>(
            inHi, inLo, Whi[0], Wlo[0], bi[0], tcol[0], t, aA, nullptr,
            HID, VAR, VAR, 2);
        node_gemm<128, 0, 64, true, false><<<gMid, 256, SM_MID>>>(
            aA, nullptr, Whi[1], Wlo[1], bi[1], tcol[1], t, aB, nullptr,
            HID, HID, HID, 16);
        node_gemm<128, 0, 64, true, false><<<gMid, 256, SM_MID>>>(
            aB, nullptr, Whi[2], Wlo[2], bi[2], tcol[2], t, aA, nullptr,
            HID, HID, HID, 16);
        node_gemm<128, 0, 64, true, false><<<gMid, 256, SM_MID>>>(
            aA, nullptr, Whi[3], Wlo[3], bi[3], tcol[3], t, aB, nullptr,
            HID, HID, HID, 16);
        node_gemm<64, 0, 64, false, true><<<gLast, 256, SM_LST>>>(
            aB, nullptr, Whi[4], Wlo[4], bi[4], tcol[4], t, nullptr, kb,
            VAR, HID, HID / 2, 8);
    };

    for (int s = 0; s < 8; s++) {
        float t0 = (float)s * dt;
        eval_f(t0, yhi, ylo);                                            // k1
        accz<<<1024, 256>>>(y, kb, kb1, acc, zhi, zlo, 1.0f, halfd, 0);  // acc=k1;  z=y+dt/2*k1
        eval_f(t0 + halfd, zhi, zlo);                                    // k2
        accz<<<1024, 256>>>(y, kb, kb1, acc, zhi, zlo, 2.0f, halfd, 1);  // acc+=2k2; z=y+dt/2*k2
        eval_f(t0 + halfd, zhi, zlo);                                    // k3
        accz<<<1024, 256>>>(y, kb, kb1, acc, zhi, zlo, 2.0f, dt, 1);     // acc+=2k3; z=y+dt*k3
        eval_f(t0 + dt, zhi, zlo);                                       // k4
        yupd<<<1024, 256>>>(y, acc, kb, kb1, yhi, ylo, sixth);           // y+=dt/6*(acc+k4)
    }

    copy_out<<<(BATCH * OUTD + 255) / 256, 256>>>(y, out);
}